// round 2
// baseline (speedup 1.0000x reference)
#include <cuda_runtime.h>
#include <cstdint>

// Problem constants
#define Nn 32
#define Cc 64
#define HW 16384            // 128*128
#define CHW (Cc*HW)         // 1048576
#define NCOLS_S 58255       // number of subsampled columns (524288 cols, stride 9)
#define NCHUNK 911          // ceil(58255/64)
#define EPSF 0.01f
#define GRID_GRAM 256
#define GRID_APPLY 2048     // 32 n * 64 p-tiles of 256

typedef unsigned long long ull;

// ---------------- f32x2 helpers (Blackwell FFMA2) ----------------
__device__ __forceinline__ ull pack2(float x, float y) {
    ull r; asm("mov.b64 %0, {%1,%2};" : "=l"(r) : "f"(x), "f"(y)); return r;
}
__device__ __forceinline__ void unpack2(ull v, float& x, float& y) {
    asm("mov.b64 {%0,%1}, %2;" : "=f"(x), "=f"(y) : "l"(v));
}
__device__ __forceinline__ void ffma2(ull& d, ull a, ull b) {
    asm("fma.rn.f32x2 %0, %1, %2, %3;" : "=l"(d) : "l"(a), "l"(b), "l"(d));
}

// ---------------- device scratch (no allocation allowed) ----------------
__device__ float g_part[GRID_GRAM * 4096];   // per-block Gram partials (4 MB)
__device__ float g_rspart[GRID_GRAM * 64];   // per-block rowsum partials
__device__ float g_gram[4096];
__device__ float g_rowsum[64];
__device__ ull   g_deconv2[4096];            // deconv[c][b] as {d,d}; [c][b] layout
__device__ float g_dmean[64];

// =====================================================================
// Pass 1: Gram of subsampled columns + row sums (deterministic partials)
// =====================================================================
__global__ void __launch_bounds__(256) gram_kernel(const float* __restrict__ x) {
    __shared__ float asub[64][64];   // [scol][b]
    __shared__ float ps[256];

    const int t = threadIdx.x;
    const int bid = blockIdx.x;
    const int b = t & 63;
    const int g = t >> 6;
    const int ti = t >> 4, tj = t & 15;
    const int i0 = ti * 4, j0 = tj * 4;

    float acc[4][4];
#pragma unroll
    for (int p = 0; p < 4; p++)
#pragma unroll
        for (int q = 0; q < 4; q++) acc[p][q] = 0.f;
    float rs = 0.f;

    for (int chunk = bid; chunk < NCHUNK; chunk += GRID_GRAM) {
        float vals[16];
#pragma unroll
        for (int k = 0; k < 16; k++) {
            const int scol = g * 16 + k;
            const int s = chunk * 64 + scol;
            float v = 0.f;
            if (s < NCOLS_S) {
                const int col = s * 9;
                const int n = col >> 14;
                const int p = col & 16383;
                v = x[n * CHW + b * HW + p];
            }
            vals[k] = v;
            rs += v;
        }
        __syncthreads();   // previous chunk's compute done before overwrite
#pragma unroll
        for (int k = 0; k < 16; k++) asub[g * 16 + k][b] = vals[k];
        __syncthreads();

#pragma unroll 4
        for (int scol = 0; scol < 64; scol++) {
            const float4 av = *(const float4*)&asub[scol][i0];
            const float4 bv = *(const float4*)&asub[scol][j0];
            const float ar[4] = {av.x, av.y, av.z, av.w};
            const float br[4] = {bv.x, bv.y, bv.z, bv.w};
#pragma unroll
            for (int p = 0; p < 4; p++)
#pragma unroll
                for (int q = 0; q < 4; q++)
                    acc[p][q] = fmaf(ar[p], br[q], acc[p][q]);
        }
    }

    float* gp = &g_part[bid * 4096];
#pragma unroll
    for (int p = 0; p < 4; p++)
#pragma unroll
        for (int q = 0; q < 4; q++)
            gp[(i0 + p) * 64 + (j0 + q)] = acc[p][q];

    __syncthreads();
    ps[t] = rs;
    __syncthreads();
    if (t < 64)
        g_rspart[bid * 64 + t] = ps[t] + ps[t + 64] + ps[t + 128] + ps[t + 192];
}

// =====================================================================
// Deterministic reduction of partials (coalesced, k-parallel)
// grid 64, block 256: 64 idx per block x 4 k-slices
// =====================================================================
__global__ void __launch_bounds__(256) reduce_kernel() {
    __shared__ float sred[256];
    const int t = threadIdx.x;
    const int li = t & 63;
    const int ks = t >> 6;
    const int idx = blockIdx.x * 64 + li;

    float s = 0.f;
    for (int k = ks; k < GRID_GRAM; k += 4)
        s += g_part[k * 4096 + idx];
    sred[ks * 64 + li] = s;
    __syncthreads();
    if (t < 64)
        g_gram[blockIdx.x * 64 + t] =
            sred[t] + sred[64 + t] + sred[128 + t] + sred[192 + t];

    if (blockIdx.x == 0) {
        float r = 0.f;
        for (int k = ks; k < GRID_GRAM; k += 4)
            r += g_rspart[k * 64 + li];
        __syncthreads();
        sred[ks * 64 + li] = r;
        __syncthreads();
        if (t < 64)
            g_rowsum[t] = sred[t] + sred[64 + t] + sred[128 + t] + sred[192 + t];
    }
}

// =====================================================================
// Newton-Schulz inverse sqrt (single block, 1024 threads)
// =====================================================================
__device__ __forceinline__ void mm64w(float* __restrict__ D,
                                      const float* __restrict__ A,
                                      const float* __restrict__ B,
                                      int i, int j0, bool thalf) {
    ull a0 = 0ull, a1 = 0ull;
#pragma unroll 16
    for (int b = 0; b < 64; b++) {
        const ulonglong2 bv = *(const ulonglong2*)(B + b * 64 + j0);
        const float av = A[i * 64 + b];
        const ull ad = pack2(av, av);
        ffma2(a0, ad, bv.x);
        ffma2(a1, ad, bv.y);
    }
    float v0, v1, v2, v3;
    unpack2(a0, v0, v1);
    unpack2(a1, v2, v3);
    if (thalf) {
        v0 = (i == j0     ? 1.5f : 0.f) - 0.5f * v0;
        v1 = (i == j0 + 1 ? 1.5f : 0.f) - 0.5f * v1;
        v2 = (i == j0 + 2 ? 1.5f : 0.f) - 0.5f * v2;
        v3 = (i == j0 + 3 ? 1.5f : 0.f) - 0.5f * v3;
    }
    float4 o; o.x = v0; o.y = v1; o.z = v2; o.w = v3;
    *(float4*)(D + i * 64 + j0) = o;
}

#define NS_SMEM ((4 * 4096 + 1024) * 4)

__global__ void __launch_bounds__(1024) ns_kernel() {
    extern __shared__ float sm[];
    float* M0 = sm;
    float* M1 = sm + 4096;
    float* M2 = sm + 8192;
    float* M3 = sm + 12288;
    float* red = sm + 16384;

    const int t = threadIdx.x;
    const int i = t >> 4;
    const int j0 = (t & 15) * 4;
    const float invn = 1.0f / (float)NCOLS_S;

    // cov = gram/ncols + eps*I into M0, accumulate Frobenius^2
    float ss = 0.f;
#pragma unroll
    for (int c = 0; c < 4; c++) {
        const int j = j0 + c;
        float v = g_gram[i * 64 + j] * invn + ((i == j) ? EPSF : 0.f);
        M0[i * 64 + j] = v;
        ss += v * v;
    }
    red[t] = ss;
    __syncthreads();
    for (int off = 512; off > 0; off >>= 1) {
        if (t < off) red[t] += red[t + off];
        __syncthreads();
    }
    const float normA = sqrtf(red[0]);
    const float inv = 1.0f / normA;

    // Y = cov/normA (M1), Z = I (M2)
#pragma unroll
    for (int c = 0; c < 4; c++) {
        const int j = j0 + c;
        M1[i * 64 + j] = M0[i * 64 + j] * inv;
        M2[i * 64 + j] = (i == j) ? 1.f : 0.f;
    }
    __syncthreads();

    float *Y = M1, *Z = M2, *T = M0, *U = M3;
    for (int it = 0; it < 5; it++) {
        mm64w(T, Z, Y, i, j0, true);   __syncthreads();   // T = 1.5I - 0.5 Z@Y
        mm64w(U, Y, T, i, j0, false);  __syncthreads();   // U = Y@T (new Y)
        mm64w(Y, T, Z, i, j0, false);  __syncthreads();   // old-Y slot = T@Z (new Z)
        float* oldY = Y; float* oldZ = Z;
        Y = U; Z = oldY; U = oldZ;
    }

    const float sc = 1.0f / sqrtf(normA);
#pragma unroll
    for (int c = 0; c < 4; c++) {
        const int j = j0 + c;
        const float d = Z[i * 64 + j] * sc;
        g_deconv2[i * 64 + j] = pack2(d, d);
    }
    __syncthreads();
    if (t < 64) {
        float dm = 0.f;
        for (int b = 0; b < 64; b++)
            dm += Z[t * 64 + b] * sc * (g_rowsum[b] * invn);
        g_dmean[t] = dm;
    }
}

// =====================================================================
// Pass 2: y = deconv @ x - dmean
// 8 channels x 8 cols per thread, b processed in pairs so each d fetch
// is a single broadcast LDS.128 {d_b,d_b; d_b1,d_b1}.
// Per b-pair per warp: 8 d-wf + 16 x-wf = 24 smem wf vs 32 fma cycles
// -> fma-pipe bound.
// =====================================================================
#define APPLY_SMEM (64 * 256 * 4 + 4096 * 8 + 64 * 4)

__global__ void __launch_bounds__(256, 2) apply_kernel(const float* __restrict__ x,
                                                       float* __restrict__ y) {
    extern __shared__ float smem[];
    float* xs = smem;                       // [64][256]
    ull*   dsp = (ull*)(smem + 16384);      // [64][64] packed {d,d}
    float* dm  = smem + 16384 + 8192;       // [64]

    const int t = threadIdx.x;
    const int bid = blockIdx.x;
    const int n = bid >> 6;
    const int p0 = (bid & 63) << 8;

    // stage deconv + dmean
#pragma unroll
    for (int k = 0; k < 16; k++) dsp[k * 256 + t] = g_deconv2[k * 256 + t];
    if (t < 64) dm[t] = g_dmean[t];

    // stage x tile [64 channels][256 cols]
    const float* xb = x + n * CHW + p0;
#pragma unroll
    for (int k = 0; k < 16; k++) {
        const int v = k * 256 + t;
        const int row = v >> 6;
        const int cv = (v & 63) << 2;
        *(float4*)&xs[row * 256 + cv] = *(const float4*)&xb[row * HW + cv];
    }
    __syncthreads();

    const int cg = t >> 5;          // 8 groups of 8 channels
    const int lane = t & 31;
    const int j0 = lane << 3;       // 8 columns per thread
    const int c0 = cg << 3;

    ull acc[8][4];
#pragma unroll
    for (int c = 0; c < 8; c++)
#pragma unroll
        for (int h = 0; h < 4; h++) acc[c][h] = 0ull;

#pragma unroll 4
    for (int bh = 0; bh < 32; bh++) {
        const int b0 = bh * 2;
        const ulonglong2 x0 = *(const ulonglong2*)&xs[b0 * 256 + j0];
        const ulonglong2 x1 = *(const ulonglong2*)&xs[b0 * 256 + j0 + 4];
        const ulonglong2 x2 = *(const ulonglong2*)&xs[(b0 + 1) * 256 + j0];
        const ulonglong2 x3 = *(const ulonglong2*)&xs[(b0 + 1) * 256 + j0 + 4];
#pragma unroll
        for (int c = 0; c < 8; c++) {
            const ulonglong2 d = *(const ulonglong2*)&dsp[(c0 + c) * 64 + b0];
            ffma2(acc[c][0], d.x, x0.x);
            ffma2(acc[c][1], d.x, x0.y);
            ffma2(acc[c][2], d.x, x1.x);
            ffma2(acc[c][3], d.x, x1.y);
            ffma2(acc[c][0], d.y, x2.x);
            ffma2(acc[c][1], d.y, x2.y);
            ffma2(acc[c][2], d.y, x3.x);
            ffma2(acc[c][3], d.y, x3.y);
        }
    }

    float* yb = y + n * CHW + p0;
#pragma unroll
    for (int c = 0; c < 8; c++) {
        const float dmv = dm[c0 + c];
        float a0, a1, a2, a3, a4, a5, a6, a7;
        unpack2(acc[c][0], a0, a1);
        unpack2(acc[c][1], a2, a3);
        unpack2(acc[c][2], a4, a5);
        unpack2(acc[c][3], a6, a7);
        float4 o0, o1;
        o0.x = a0 - dmv; o0.y = a1 - dmv; o0.z = a2 - dmv; o0.w = a3 - dmv;
        o1.x = a4 - dmv; o1.y = a5 - dmv; o1.z = a6 - dmv; o1.w = a7 - dmv;
        float* yr = &yb[(c0 + c) * HW + j0];
        *(float4*)yr = o0;
        *(float4*)(yr + 4) = o1;
    }
}

// =====================================================================
extern "C" void kernel_launch(void* const* d_in, const int* in_sizes, int n_in,
                              void* d_out, int out_size) {
    (void)in_sizes; (void)n_in; (void)out_size;
    const float* x = (const float*)d_in[0];
    float* y = (float*)d_out;

    cudaFuncSetAttribute(ns_kernel, cudaFuncAttributeMaxDynamicSharedMemorySize, NS_SMEM);
    cudaFuncSetAttribute(apply_kernel, cudaFuncAttributeMaxDynamicSharedMemorySize, APPLY_SMEM);

    gram_kernel<<<GRID_GRAM, 256>>>(x);
    reduce_kernel<<<64, 256>>>();
    ns_kernel<<<1, 1024, NS_SMEM>>>();
    apply_kernel<<<GRID_APPLY, 256, APPLY_SMEM>>>(x, y);
}

// round 6
// speedup vs baseline: 1.5177x; 1.5177x over previous
#include <cuda_runtime.h>
#include <cstdint>

// Problem constants
#define Nn 32
#define Cc 64
#define HW 16384            // 128*128
#define CHW (Cc*HW)         // 1048576
#define NCOLS_S 58255
#define NCHUNK 911
#define EPSF 0.01f
#define GRID_GRAM 148
#define GRID_APPLY 2048     // 524288 cols / 256 per block

typedef unsigned long long ull;
typedef unsigned int u32;

// ---------------- f32x2 helpers ----------------
__device__ __forceinline__ ull pack2(float x, float y) {
    ull r; asm("mov.b64 %0, {%1,%2};" : "=l"(r) : "f"(x), "f"(y)); return r;
}
__device__ __forceinline__ void unpack2(ull v, float& x, float& y) {
    asm("mov.b64 {%0,%1}, %2;" : "=f"(x), "=f"(y) : "l"(v));
}
__device__ __forceinline__ void ffma2(ull& d, ull a, ull b) {
    asm("fma.rn.f32x2 %0, %1, %2, %3;" : "=l"(d) : "l"(a), "l"(b), "l"(d));
}

// bf16x2 pack: hi16 = bf16(a), lo16 = bf16(b)
__device__ __forceinline__ u32 bf2(float a_hi, float b_lo) {
    u32 r; asm("cvt.rn.bf16x2.f32 %0, %1, %2;" : "=r"(r) : "f"(a_hi), "f"(b_lo));
    return r;
}

__device__ __forceinline__ u32 smem_u32(const void* p) {
    u32 a;
    asm("{ .reg .u64 t; cvta.to.shared.u64 t, %1; cvt.u32.u64 %0, t; }" : "=r"(a) : "l"(p));
    return a;
}

// ---------------- mma.sync helpers (sm_80 ISA, runs on Blackwell HMMA) ----
__device__ __forceinline__ void ldm_x4(u32& r0, u32& r1, u32& r2, u32& r3, u32 addr) {
    asm volatile("ldmatrix.sync.aligned.m8n8.x4.shared.b16 {%0,%1,%2,%3}, [%4];"
                 : "=r"(r0), "=r"(r1), "=r"(r2), "=r"(r3) : "r"(addr));
}
__device__ __forceinline__ void ldm_x2t(u32& r0, u32& r1, u32 addr) {
    asm volatile("ldmatrix.sync.aligned.m8n8.x2.trans.shared.b16 {%0,%1}, [%2];"
                 : "=r"(r0), "=r"(r1) : "r"(addr));
}
__device__ __forceinline__ void mma_bf16(float* d, const u32* a, const u32* b) {
    asm volatile(
        "mma.sync.aligned.m16n8k16.row.col.f32.bf16.bf16.f32 "
        "{%0,%1,%2,%3}, {%4,%5,%6,%7}, {%8,%9}, {%0,%1,%2,%3};"
        : "+f"(d[0]), "+f"(d[1]), "+f"(d[2]), "+f"(d[3])
        : "r"(a[0]), "r"(a[1]), "r"(a[2]), "r"(a[3]), "r"(b[0]), "r"(b[1]));
}

// ---------------- device scratch ----------------
__device__ float g_part[GRID_GRAM * 4096];
__device__ float g_rspart[GRID_GRAM * 64];
__device__ float g_gram[4096];
__device__ float g_rowsum[64];
__device__ __align__(16) u32 g_wpack[4096];   // [0:2048) Wh, [2048:4096) Wl  (row-major [64][32] u32)
__device__ float g_dmean[64];

// =====================================================================
// Pass 1: Gram of subsampled columns + row sums
// =====================================================================
__global__ void __launch_bounds__(256) gram_kernel(const float* __restrict__ x) {
    __shared__ float asub[64][64];
    __shared__ float ps[256];

    const int t = threadIdx.x;
    const int bid = blockIdx.x;
    const int b = t & 63;
    const int g = t >> 6;
    const int i0 = (t >> 4) * 4, j0 = (t & 15) * 4;

    float acc[4][4];
#pragma unroll
    for (int p = 0; p < 4; p++)
#pragma unroll
        for (int q = 0; q < 4; q++) acc[p][q] = 0.f;
    float rs = 0.f;

    for (int chunk = bid; chunk < NCHUNK; chunk += GRID_GRAM) {
        float vals[16];
#pragma unroll
        for (int k = 0; k < 16; k++) {
            const int scol = g * 16 + k;
            const int s = chunk * 64 + scol;
            float v = 0.f;
            if (s < NCOLS_S) {
                const int col = s * 9;
                const int n = col >> 14;
                const int p = col & 16383;
                v = x[n * CHW + b * HW + p];
            }
            vals[k] = v;
            rs += v;
        }
        __syncthreads();
#pragma unroll
        for (int k = 0; k < 16; k++) asub[g * 16 + k][b] = vals[k];
        __syncthreads();

#pragma unroll 4
        for (int scol = 0; scol < 64; scol++) {
            const float4 av = *(const float4*)&asub[scol][i0];
            const float4 bv = *(const float4*)&asub[scol][j0];
            const float ar[4] = {av.x, av.y, av.z, av.w};
            const float br[4] = {bv.x, bv.y, bv.z, bv.w};
#pragma unroll
            for (int p = 0; p < 4; p++)
#pragma unroll
                for (int q = 0; q < 4; q++)
                    acc[p][q] = fmaf(ar[p], br[q], acc[p][q]);
        }
    }

    float* gp = &g_part[bid * 4096];
#pragma unroll
    for (int p = 0; p < 4; p++)
#pragma unroll
        for (int q = 0; q < 4; q++)
            gp[(i0 + p) * 64 + (j0 + q)] = acc[p][q];

    __syncthreads();
    ps[t] = rs;
    __syncthreads();
    if (t < 64)
        g_rspart[bid * 64 + t] = ps[t] + ps[t + 64] + ps[t + 128] + ps[t + 192];
}

// =====================================================================
// Deterministic reduction
// =====================================================================
__global__ void __launch_bounds__(256) reduce_kernel() {
    const int idx = blockIdx.x * 256 + threadIdx.x;
    float s = 0.f;
    for (int k = 0; k < GRID_GRAM; k++) s += g_part[k * 4096 + idx];
    g_gram[idx] = s;
    if (blockIdx.x == 0 && threadIdx.x < 64) {
        float r = 0.f;
        for (int k = 0; k < GRID_GRAM; k++) r += g_rspart[k * 64 + threadIdx.x];
        g_rowsum[threadIdx.x] = r;
    }
}

// =====================================================================
// Newton-Schulz (256 threads) + bf16 W hi/lo emission (plain row-major)
// =====================================================================
__device__ __forceinline__ void mm64(float* __restrict__ D,
                                     const float* __restrict__ A,
                                     const float* __restrict__ B,
                                     int t, bool thalf) {
    const int i0 = (t >> 4) * 4, j0 = (t & 15) * 4;
    ull acc[4][2];
#pragma unroll
    for (int a = 0; a < 4; a++) { acc[a][0] = 0ull; acc[a][1] = 0ull; }

#pragma unroll 8
    for (int b = 0; b < 64; b++) {
        const ulonglong2 bv = *(const ulonglong2*)(B + b * 64 + j0);
#pragma unroll
        for (int a = 0; a < 4; a++) {
            const float av = A[(i0 + a) * 64 + b];
            const ull ad = pack2(av, av);
            ffma2(acc[a][0], ad, bv.x);
            ffma2(acc[a][1], ad, bv.y);
        }
    }
#pragma unroll
    for (int a = 0; a < 4; a++) {
        const int i = i0 + a;
#pragma unroll
        for (int h = 0; h < 2; h++) {
            float vx, vy; unpack2(acc[a][h], vx, vy);
            const int j = j0 + h * 2;
            if (thalf) {
                vx = (i == j     ? 1.5f : 0.f) - 0.5f * vx;
                vy = (i == j + 1 ? 1.5f : 0.f) - 0.5f * vy;
            }
            D[i * 64 + j]     = vx;
            D[i * 64 + j + 1] = vy;
        }
    }
}

#define NS_SMEM ((4 * 4096 + 256) * 4)

__global__ void __launch_bounds__(256) ns_kernel() {
    extern __shared__ float sm[];
    float* M0 = sm;
    float* M1 = sm + 4096;
    float* M2 = sm + 8192;
    float* M3 = sm + 12288;
    float* red = sm + 16384;

    const int t = threadIdx.x;
    const int i0 = (t >> 4) * 4, j0 = (t & 15) * 4;
    const float invn = 1.0f / (float)NCOLS_S;

    float ss = 0.f;
#pragma unroll
    for (int a = 0; a < 4; a++)
#pragma unroll
        for (int c = 0; c < 4; c++) {
            const int i = i0 + a, j = j0 + c;
            float v = g_gram[i * 64 + j] * invn + ((i == j) ? EPSF : 0.f);
            M0[i * 64 + j] = v;
            ss += v * v;
        }
    red[t] = ss;
    __syncthreads();
    for (int off = 128; off > 0; off >>= 1) {
        if (t < off) red[t] += red[t + off];
        __syncthreads();
    }
    const float normA = sqrtf(red[0]);
    const float inv = 1.0f / normA;

#pragma unroll
    for (int a = 0; a < 4; a++)
#pragma unroll
        for (int c = 0; c < 4; c++) {
            const int i = i0 + a, j = j0 + c;
            M1[i * 64 + j] = M0[i * 64 + j] * inv;
            M2[i * 64 + j] = (i == j) ? 1.f : 0.f;
        }
    __syncthreads();

    float *Y = M1, *Z = M2, *T = M0, *U = M3;
    for (int it = 0; it < 5; it++) {
        mm64(T, Z, Y, t, true);   __syncthreads();
        mm64(U, Y, T, t, false);  __syncthreads();
        mm64(Y, T, Z, t, false);  __syncthreads();
        float* oldY = Y; float* oldZ = Z;
        Y = U; Z = oldY; U = oldZ;
    }

    const float sc = 1.0f / sqrtf(normA);
    // W row-major [ch_out][ch_in] bf16 hi/lo, u32 = {low: j, high: j+1}
#pragma unroll
    for (int a = 0; a < 4; a++) {
        const int i = i0 + a;
#pragma unroll
        for (int cp = 0; cp < 2; cp++) {
            const int j = j0 + cp * 2;
            const float d0 = Z[i * 64 + j] * sc;
            const float d1 = Z[i * 64 + j + 1] * sc;
            const u32 h = bf2(d1, d0);
            const float r0 = d0 - __uint_as_float(h << 16);
            const float r1 = d1 - __uint_as_float(h & 0xFFFF0000u);
            const u32 l = bf2(r1, r0);
            const u32 idx = i * 32 + (j >> 1);
            g_wpack[idx] = h;
            g_wpack[2048 + idx] = l;
        }
    }
    __syncthreads();
    if (t < 64) {
        float dm = 0.f;
        for (int b = 0; b < 64; b++)
            dm += Z[t * 64 + b] * sc * (g_rowsum[b] * invn);
        g_dmean[t] = dm;
    }
}

// =====================================================================
// Pass 2 (mma.sync bf16 split-precision):
//   y[ch_out][col] = sum_ch W[ch_out][ch] * x[ch][col] - dmean[ch_out]
//   D += Wh@Xh + Wh@Xl + Wl@Xh   (f32 accumulators)
// Block: 256 thr (8 warps), 256 cols; warp strip = 32 cols, M=64 whole.
// Smem: Xh/Xl [64][264] bf16 (row 528B -> ldmatrix conflict-free),
//       Wh/Wl [64][72] bf16 (row 144B -> conflict-free), dmean.
// =====================================================================
#define XSTRIDE_H 264              // bf16 elems per X row
#define SM_XH 0
#define SM_XL 33792
#define SM_WH 67584
#define SM_WL 76800
#define SM_DM 86016
#define APPLY_SMEM (SM_DM + 256)

__global__ void __launch_bounds__(256, 2) apply_mma_kernel(const float* __restrict__ x,
                                                           float* __restrict__ y) {
    extern __shared__ char smc[];
    const u32 sbase = smem_u32(smc);
    const int t = threadIdx.x;
    const int wid = t >> 5;
    const int lane = t & 31;

    // ---- stage W (padded rows: 36 u32 = 72 bf16) + dmean ----
    {
        u32* wh = (u32*)(smc + SM_WH);
        u32* wl = (u32*)(smc + SM_WL);
#pragma unroll
        for (int k = 0; k < 8; k++) {
            const int u = k * 256 + t;          // 0..2047
            const int i = u >> 5;
            const int jc = u & 31;
            wh[i * 36 + jc] = g_wpack[u];
            wl[i * 36 + jc] = g_wpack[2048 + u];
        }
        if (t < 64) ((float*)(smc + SM_DM))[t] = g_dmean[t];
    }

    // ---- stage X tile: convert f32 -> bf16 hi/lo ----
    const int gcol0 = blockIdx.x * 256;
    const int n = gcol0 >> 14;
    const int p0 = gcol0 & 16383;
    const float* xb = x + (size_t)n * CHW + p0;

    {
        const int c = (t & 63) * 4;             // col within tile
        const int row0 = (t >> 6) * 16;
        ull* xhp = (ull*)(smc + SM_XH);
        ull* xlp = (ull*)(smc + SM_XL);
#pragma unroll
        for (int r = 0; r < 16; r++) {
            const int row = row0 + r;
            const float4 v = *(const float4*)&xb[(size_t)row * HW + c];
            const u32 h0 = bf2(v.y, v.x);
            const u32 h1 = bf2(v.w, v.z);
            const float r0 = v.x - __uint_as_float(h0 << 16);
            const float r1 = v.y - __uint_as_float(h0 & 0xFFFF0000u);
            const float r2 = v.z - __uint_as_float(h1 << 16);
            const float r3 = v.w - __uint_as_float(h1 & 0xFFFF0000u);
            const u32 l0 = bf2(r1, r0);
            const u32 l1 = bf2(r3, r2);
            const int di = (row * XSTRIDE_H + c) >> 2;   // ull index (8B)
            xhp[di] = ((ull)h1 << 32) | h0;
            xlp[di] = ((ull)l1 << 32) | l0;
        }
    }
    __syncthreads();

    // ---- MMA mainloop ----
    const int wc0 = wid * 32;                  // warp's col strip
    float d[4][4][4];                          // [mi][ni][reg]
#pragma unroll
    for (int mi = 0; mi < 4; mi++)
#pragma unroll
        for (int ni = 0; ni < 4; ni++)
#pragma unroll
            for (int r = 0; r < 4; r++) d[mi][ni][r] = 0.f;

    // ldmatrix lane addressing
    const int arow = lane & 15;                // A: row within 16
    const int aseg = (lane >> 4) * 8;          // A: k sub-block (elements)
    const u32 a_h_base = sbase + SM_WH + (u32)arow * 144 + (u32)aseg * 2;
    const u32 a_l_base = sbase + SM_WL + (u32)arow * 144 + (u32)aseg * 2;
    const int brow = lane & 15;                // B: k row
    const u32 b_h_base = sbase + SM_XH + (u32)brow * 528 + (u32)wc0 * 2;
    const u32 b_l_base = sbase + SM_XL + (u32)brow * 528 + (u32)wc0 * 2;

#pragma unroll
    for (int ks = 0; ks < 4; ks++) {
        // B fragments for 4 n-tiles, hi+lo
        u32 bh[4][2], bl[4][2];
#pragma unroll
        for (int ni = 0; ni < 4; ni++) {
            ldm_x2t(bh[ni][0], bh[ni][1], b_h_base + (u32)(ks * 16) * 528 + (u32)ni * 16);
            ldm_x2t(bl[ni][0], bl[ni][1], b_l_base + (u32)(ks * 16) * 528 + (u32)ni * 16);
        }
#pragma unroll
        for (int mh = 0; mh < 2; mh++) {
            u32 ah[2][4], al[2][4];
#pragma unroll
            for (int m2 = 0; m2 < 2; m2++) {
                const int mi = mh * 2 + m2;
                const u32 aoff = (u32)(mi * 16) * 144 + (u32)(ks * 16) * 2;
                ldm_x4(ah[m2][0], ah[m2][1], ah[m2][2], ah[m2][3], a_h_base + aoff);
                ldm_x4(al[m2][0], al[m2][1], al[m2][2], al[m2][3], a_l_base + aoff);
            }
#pragma unroll
            for (int m2 = 0; m2 < 2; m2++) {
                const int mi = mh * 2 + m2;
#pragma unroll
                for (int ni = 0; ni < 4; ni++) {
                    mma_bf16(d[mi][ni], ah[m2], bh[ni]);
                    mma_bf16(d[mi][ni], ah[m2], bl[ni]);
                    mma_bf16(d[mi][ni], al[m2], bh[ni]);
                }
            }
        }
    }

    // ---- epilogue ----
    const float* dmean = (const float*)(smc + SM_DM);
    float* yb = y + (size_t)n * CHW + p0;
    const int nlo = (lane & 3) * 2;
    const int mrow = lane >> 2;
#pragma unroll
    for (int mi = 0; mi < 4; mi++) {
        const int ch0 = mi * 16 + mrow;
        const float dm0 = dmean[ch0];
        const float dm1 = dmean[ch0 + 8];
#pragma unroll
        for (int ni = 0; ni < 4; ni++) {
            const int col = wc0 + ni * 8 + nlo;
            float2 o0, o1;
            o0.x = d[mi][ni][0] - dm0; o0.y = d[mi][ni][1] - dm0;
            o1.x = d[mi][ni][2] - dm1; o1.y = d[mi][ni][3] - dm1;
            *(float2*)&yb[(size_t)ch0 * HW + col] = o0;
            *(float2*)&yb[(size_t)(ch0 + 8) * HW + col] = o1;
        }
    }
}

// =====================================================================
extern "C" void kernel_launch(void* const* d_in, const int* in_sizes, int n_in,
                              void* d_out, int out_size) {
    (void)in_sizes; (void)n_in; (void)out_size;
    const float* x = (const float*)d_in[0];
    float* y = (float*)d_out;

    cudaFuncSetAttribute(ns_kernel, cudaFuncAttributeMaxDynamicSharedMemorySize, NS_SMEM);
    cudaFuncSetAttribute(apply_mma_kernel, cudaFuncAttributeMaxDynamicSharedMemorySize, APPLY_SMEM);

    gram_kernel<<<GRID_GRAM, 256>>>(x);
    reduce_kernel<<<16, 256>>>();
    ns_kernel<<<1, 256, NS_SMEM>>>();
    apply_mma_kernel<<<GRID_APPLY, 256, APPLY_SMEM>>>(x, y);
}

// round 7
// speedup vs baseline: 1.8328x; 1.2075x over previous
#include <cuda_runtime.h>
#include <cstdint>

// Problem constants
#define Nn 32
#define Cc 64
#define HW 16384            // 128*128
#define CHW (Cc*HW)         // 1048576
#define NCOLS_S 58255
#define NCHUNK 911
#define EPSF 0.01f
#define GRID_GRAM 148
#define GRID_APPLY 4096     // 524288 cols / 128 per block

typedef unsigned long long ull;
typedef unsigned int u32;

// ---------------- f32x2 helpers ----------------
__device__ __forceinline__ ull pack2(float x, float y) {
    ull r; asm("mov.b64 %0, {%1,%2};" : "=l"(r) : "f"(x), "f"(y)); return r;
}
__device__ __forceinline__ void unpack2(ull v, float& x, float& y) {
    asm("mov.b64 {%0,%1}, %2;" : "=f"(x), "=f"(y) : "l"(v));
}
__device__ __forceinline__ void ffma2(ull& d, ull a, ull b) {
    asm("fma.rn.f32x2 %0, %1, %2, %3;" : "=l"(d) : "l"(a), "l"(b), "l"(d));
}

// bf16x2 pack: high 16 bits = bf16(a_hi), low 16 = bf16(b_lo)
__device__ __forceinline__ u32 bf2(float a_hi, float b_lo) {
    u32 r; asm("cvt.rn.bf16x2.f32 %0, %1, %2;" : "=r"(r) : "f"(a_hi), "f"(b_lo));
    return r;
}
// unpack bf16x2 -> two f32
__device__ __forceinline__ void ubf2(u32 v, float& lo, float& hi) {
    lo = __uint_as_float(v << 16);
    hi = __uint_as_float(v & 0xFFFF0000u);
}

__device__ __forceinline__ u32 smem_u32(const void* p) {
    u32 a;
    asm("{ .reg .u64 t; cvta.to.shared.u64 t, %1; cvt.u32.u64 %0, t; }" : "=r"(a) : "l"(p));
    return a;
}

// ---------------- mma.sync helpers ----------------
__device__ __forceinline__ void ldm_x4(u32& r0, u32& r1, u32& r2, u32& r3, u32 addr) {
    asm volatile("ldmatrix.sync.aligned.m8n8.x4.shared.b16 {%0,%1,%2,%3}, [%4];"
                 : "=r"(r0), "=r"(r1), "=r"(r2), "=r"(r3) : "r"(addr));
}
__device__ __forceinline__ void ldm_x2t(u32& r0, u32& r1, u32 addr) {
    asm volatile("ldmatrix.sync.aligned.m8n8.x2.trans.shared.b16 {%0,%1}, [%2];"
                 : "=r"(r0), "=r"(r1) : "r"(addr));
}
__device__ __forceinline__ void mma_bf16(float* d, const u32* a, const u32* b) {
    asm volatile(
        "mma.sync.aligned.m16n8k16.row.col.f32.bf16.bf16.f32 "
        "{%0,%1,%2,%3}, {%4,%5,%6,%7}, {%8,%9}, {%0,%1,%2,%3};"
        : "+f"(d[0]), "+f"(d[1]), "+f"(d[2]), "+f"(d[3])
        : "r"(a[0]), "r"(a[1]), "r"(a[2]), "r"(a[3]), "r"(b[0]), "r"(b[1]));
}

// ---------------- device scratch ----------------
__device__ float g_part[GRID_GRAM * 4096];
__device__ float g_rspart[GRID_GRAM * 64];
__device__ float g_gram[4096];
__device__ float g_rowsum[64];
__device__ __align__(16) u32 g_wpack[4096];   // [0:2048) Wh, [2048:4096) Wl  (row-major [64][32] u32)
__device__ float g_dmean[64];

// =====================================================================
// Pass 1: Gram of subsampled columns + row sums
// =====================================================================
__global__ void __launch_bounds__(256) gram_kernel(const float* __restrict__ x) {
    __shared__ float asub[64][64];
    __shared__ float ps[256];

    const int t = threadIdx.x;
    const int bid = blockIdx.x;
    const int b = t & 63;
    const int g = t >> 6;
    const int i0 = (t >> 4) * 4, j0 = (t & 15) * 4;

    float acc[4][4];
#pragma unroll
    for (int p = 0; p < 4; p++)
#pragma unroll
        for (int q = 0; q < 4; q++) acc[p][q] = 0.f;
    float rs = 0.f;

    for (int chunk = bid; chunk < NCHUNK; chunk += GRID_GRAM) {
        float vals[16];
#pragma unroll
        for (int k = 0; k < 16; k++) {
            const int scol = g * 16 + k;
            const int s = chunk * 64 + scol;
            float v = 0.f;
            if (s < NCOLS_S) {
                const int col = s * 9;
                const int n = col >> 14;
                const int p = col & 16383;
                v = x[n * CHW + b * HW + p];
            }
            vals[k] = v;
            rs += v;
        }
        __syncthreads();
#pragma unroll
        for (int k = 0; k < 16; k++) asub[g * 16 + k][b] = vals[k];
        __syncthreads();

#pragma unroll 4
        for (int scol = 0; scol < 64; scol++) {
            const float4 av = *(const float4*)&asub[scol][i0];
            const float4 bv = *(const float4*)&asub[scol][j0];
            const float ar[4] = {av.x, av.y, av.z, av.w};
            const float br[4] = {bv.x, bv.y, bv.z, bv.w};
#pragma unroll
            for (int p = 0; p < 4; p++)
#pragma unroll
                for (int q = 0; q < 4; q++)
                    acc[p][q] = fmaf(ar[p], br[q], acc[p][q]);
        }
    }

    float* gp = &g_part[bid * 4096];
#pragma unroll
    for (int p = 0; p < 4; p++)
#pragma unroll
        for (int q = 0; q < 4; q++)
            gp[(i0 + p) * 64 + (j0 + q)] = acc[p][q];

    __syncthreads();
    ps[t] = rs;
    __syncthreads();
    if (t < 64)
        g_rspart[bid * 64 + t] = ps[t] + ps[t + 64] + ps[t + 128] + ps[t + 192];
}

// =====================================================================
// Deterministic reduction
// =====================================================================
__global__ void __launch_bounds__(256) reduce_kernel() {
    const int idx = blockIdx.x * 256 + threadIdx.x;
    float s = 0.f;
    for (int k = 0; k < GRID_GRAM; k++) s += g_part[k * 4096 + idx];
    g_gram[idx] = s;
    if (blockIdx.x == 0 && threadIdx.x < 64) {
        float r = 0.f;
        for (int k = 0; k < GRID_GRAM; k++) r += g_rspart[k * 64 + threadIdx.x];
        g_rowsum[threadIdx.x] = r;
    }
}

// =====================================================================
// Newton-Schulz via mma.sync (single block, 256 thr = 8 warps)
// Matrices kept as bf16 hi/lo images: [64 rows][72 bf16] (144B rows).
// 4 slots rotate (Y, Z, T, U). Each mm64: D = A@B (3-term split).
// Warp w: m-tile = w&3 (16 rows), n-half = w>>2 (32 cols).
// =====================================================================
#define SLOT_BYTES 18432           // hi(9216) + lo(9216)
#define NS_SMEM (4 * SLOT_BYTES + 1024)

__device__ __forceinline__ void ns_mm64(char* smc, u32 sbase,
                                        int dst, int As, int Bs,
                                        int wid, int lane, bool thalf) {
    const int mt = wid & 3;
    const int nh = wid >> 2;

    float d[4][4];
#pragma unroll
    for (int nt = 0; nt < 4; nt++)
#pragma unroll
        for (int r = 0; r < 4; r++) d[nt][r] = 0.f;

    const u32 Ahi = sbase + (u32)As * SLOT_BYTES;
    const u32 Alo = Ahi + 9216;
    const u32 Bhi = sbase + (u32)Bs * SLOT_BYTES;
    const u32 Blo = Bhi + 9216;

    const u32 a_base = (u32)(mt * 16 + (lane & 15)) * 144 + (u32)(lane >> 4) * 16;
    const u32 b_base = (u32)(lane & 15) * 144 + (u32)nh * 64;

#pragma unroll
    for (int ks = 0; ks < 4; ks++) {
        u32 ah[4], al[4];
        ldm_x4(ah[0], ah[1], ah[2], ah[3], Ahi + a_base + (u32)ks * 32);
        ldm_x4(al[0], al[1], al[2], al[3], Alo + a_base + (u32)ks * 32);
        const u32 brow = b_base + (u32)(ks * 16) * 144;
#pragma unroll
        for (int nt = 0; nt < 4; nt++) {
            u32 bh[2], bl[2];
            ldm_x2t(bh[0], bh[1], Bhi + brow + (u32)nt * 16);
            ldm_x2t(bl[0], bl[1], Blo + brow + (u32)nt * 16);
            mma_bf16(d[nt], ah, bh);
            mma_bf16(d[nt], ah, bl);
            mma_bf16(d[nt], al, bh);
        }
    }

    // post-op + write bf16 hi/lo images of result
    u32* Dhi = (u32*)(smc + dst * SLOT_BYTES);
    u32* Dlo = (u32*)(smc + dst * SLOT_BYTES + 9216);
    const int r0 = mt * 16 + (lane >> 2);
#pragma unroll
    for (int nt = 0; nt < 4; nt++) {
        const int c0 = nh * 32 + nt * 8 + (lane & 3) * 2;
        float v0 = d[nt][0], v1 = d[nt][1], v2 = d[nt][2], v3 = d[nt][3];
        if (thalf) {
            v0 = (r0 == c0     ? 1.5f : 0.f) - 0.5f * v0;
            v1 = (r0 == c0 + 1 ? 1.5f : 0.f) - 0.5f * v1;
            v2 = (r0 + 8 == c0     ? 1.5f : 0.f) - 0.5f * v2;
            v3 = (r0 + 8 == c0 + 1 ? 1.5f : 0.f) - 0.5f * v3;
        }
        {
            const u32 h = bf2(v1, v0);
            float e0, e1; ubf2(h, e0, e1);
            Dhi[r0 * 36 + (c0 >> 1)] = h;
            Dlo[r0 * 36 + (c0 >> 1)] = bf2(v1 - e1, v0 - e0);
        }
        {
            const u32 h = bf2(v3, v2);
            float e2, e3; ubf2(h, e2, e3);
            Dhi[(r0 + 8) * 36 + (c0 >> 1)] = h;
            Dlo[(r0 + 8) * 36 + (c0 >> 1)] = bf2(v3 - e3, v2 - e2);
        }
    }
}

__global__ void __launch_bounds__(256) ns_kernel() {
    extern __shared__ char smc[];
    const u32 sbase = smem_u32(smc);
    float* red = (float*)(smc + 4 * SLOT_BYTES);

    const int t = threadIdx.x;
    const int wid = t >> 5;
    const int lane = t & 31;
    const float invn = 1.0f / (float)NCOLS_S;

    // ---- prologue: cov values (16 per thread), Frobenius norm ----
    const int prow = t >> 2;
    const int pcol0 = (t & 3) * 16;
    float v[16];
    float ss = 0.f;
#pragma unroll
    for (int c = 0; c < 16; c++) {
        const int j = pcol0 + c;
        float val = g_gram[prow * 64 + j] * invn + ((prow == j) ? EPSF : 0.f);
        v[c] = val;
        ss += val * val;
    }
    red[t] = ss;
    __syncthreads();
    for (int off = 128; off > 0; off >>= 1) {
        if (t < off) red[t] += red[t + off];
        __syncthreads();
    }
    const float normA = sqrtf(red[0]);
    const float inv = 1.0f / normA;

    // ---- build Y = cov/normA images (slot0), Z = I images (slot1) ----
    {
        u32* Yhi = (u32*)(smc);
        u32* Ylo = (u32*)(smc + 9216);
        u32* Zhi = (u32*)(smc + SLOT_BYTES);
        u32* Zlo = (u32*)(smc + SLOT_BYTES + 9216);
#pragma unroll
        for (int p = 0; p < 8; p++) {
            const float y0 = v[2 * p] * inv;
            const float y1 = v[2 * p + 1] * inv;
            const u32 h = bf2(y1, y0);
            float e0, e1; ubf2(h, e0, e1);
            const int ui = prow * 36 + (pcol0 >> 1) + p;
            Yhi[ui] = h;
            Ylo[ui] = bf2(y1 - e1, y0 - e0);
            // identity
            const int c0 = pcol0 + 2 * p;
            u32 ih = 0;
            if (prow == c0) ih = 0x00003F80u;
            else if (prow == c0 + 1) ih = 0x3F800000u;
            Zhi[ui] = ih;
            Zlo[ui] = 0u;
        }
    }
    __syncthreads();

    // ---- 5 NS iterations: T = 1.5I - 0.5 Z@Y; Y' = Y@T; Z' = T@Z ----
    int Y = 0, Z = 1, T = 2, U = 3;
    for (int it = 0; it < 5; it++) {
        ns_mm64(smc, sbase, T, Z, Y, wid, lane, true);   __syncthreads();
        ns_mm64(smc, sbase, U, Y, T, wid, lane, false);  __syncthreads();
        ns_mm64(smc, sbase, Y, T, Z, wid, lane, false);  __syncthreads();  // Z' into old Y
        const int oldY = Y, oldZ = Z;
        Y = U; Z = oldY; U = oldZ;
    }

    const float sc = 1.0f / sqrtf(normA);
    const u32* Zhi = (const u32*)(smc + Z * SLOT_BYTES);
    const u32* Zlo = (const u32*)(smc + Z * SLOT_BYTES + 9216);

    // ---- emit W hi/lo (row-major [64][32] u32) ----
#pragma unroll
    for (int p = 0; p < 8; p++) {
        const int ui = prow * 36 + (pcol0 >> 1) + p;
        float h0, h1, l0, l1;
        ubf2(Zhi[ui], h0, h1);
        ubf2(Zlo[ui], l0, l1);
        const float d0 = (h0 + l0) * sc;
        const float d1 = (h1 + l1) * sc;
        const u32 h = bf2(d1, d0);
        float e0, e1; ubf2(h, e0, e1);
        const u32 gi = prow * 32 + (pcol0 >> 1) + p;
        g_wpack[gi] = h;
        g_wpack[2048 + gi] = bf2(d1 - e1, d0 - e0);
    }
    __syncthreads();
    if (t < 64) {
        float dm = 0.f;
        for (int p = 0; p < 32; p++) {
            float h0, h1, l0, l1;
            ubf2(Zhi[t * 36 + p], h0, h1);
            ubf2(Zlo[t * 36 + p], l0, l1);
            dm += (h0 + l0) * sc * (g_rowsum[2 * p] * invn);
            dm += (h1 + l1) * sc * (g_rowsum[2 * p + 1] * invn);
        }
        g_dmean[t] = dm;
    }
}

// =====================================================================
// Pass 2 (mma.sync bf16 split-precision), 128-col tiles for occupancy.
//   D += Wh@Xh + Wh@Xl + Wl@Xh
// Block: 256 thr (8 warps), 128 cols; warp strip = 16 cols (2 n-tiles).
// Smem: Xh/Xl [64][136] bf16 (272B rows), Wh/Wl [64][72] bf16, dmean.
// =====================================================================
#define XSTRIDE_H 136              // bf16 elems per X row (272B = 17x16B)
#define SM_XH 0
#define SM_XL 17408
#define SM_WH 34816
#define SM_WL 44032
#define SM_DM 53248
#define APPLY_SMEM (SM_DM + 256)

__global__ void __launch_bounds__(256, 3) apply_mma_kernel(const float* __restrict__ x,
                                                           float* __restrict__ y) {
    extern __shared__ char smc[];
    const u32 sbase = smem_u32(smc);
    const int t = threadIdx.x;
    const int wid = t >> 5;
    const int lane = t & 31;

    // ---- stage W (padded rows: 36 u32 = 72 bf16) + dmean ----
    {
        u32* wh = (u32*)(smc + SM_WH);
        u32* wl = (u32*)(smc + SM_WL);
#pragma unroll
        for (int k = 0; k < 8; k++) {
            const int u = k * 256 + t;          // 0..2047
            const int i = u >> 5;
            const int jc = u & 31;
            wh[i * 36 + jc] = g_wpack[u];
            wl[i * 36 + jc] = g_wpack[2048 + u];
        }
        if (t < 64) ((float*)(smc + SM_DM))[t] = g_dmean[t];
    }

    // ---- stage X tile (64 rows x 128 cols): f32 -> bf16 hi/lo ----
    const int gcol0 = blockIdx.x * 128;
    const int n = gcol0 >> 14;
    const int p0 = gcol0 & 16383;
    const float* xb = x + (size_t)n * CHW + p0;

    {
        const int c = (lane) * 4;               // col within tile (0..124)
        const int row0 = wid * 8;
        ull* xhp = (ull*)(smc + SM_XH);
        ull* xlp = (ull*)(smc + SM_XL);
#pragma unroll
        for (int r = 0; r < 8; r++) {
            const int row = row0 + r;
            const float4 vv = *(const float4*)&xb[(size_t)row * HW + c];
            const u32 h0 = bf2(vv.y, vv.x);
            const u32 h1 = bf2(vv.w, vv.z);
            float e0, e1, e2, e3;
            ubf2(h0, e0, e1);
            ubf2(h1, e2, e3);
            const u32 l0 = bf2(vv.y - e1, vv.x - e0);
            const u32 l1 = bf2(vv.w - e3, vv.z - e2);
            const int di = (row * XSTRIDE_H + c) >> 2;   // ull index (8B)
            xhp[di] = ((ull)h1 << 32) | h0;
            xlp[di] = ((ull)l1 << 32) | l0;
        }
    }
    __syncthreads();

    // ---- MMA mainloop ----
    const int wc0 = wid * 16;                  // warp's col strip (2 n-tiles)
    float d[4][2][4];                          // [mi][ni][reg]
#pragma unroll
    for (int mi = 0; mi < 4; mi++)
#pragma unroll
        for (int ni = 0; ni < 2; ni++)
#pragma unroll
            for (int r = 0; r < 4; r++) d[mi][ni][r] = 0.f;

    const int arow = lane & 15;
    const int aseg = (lane >> 4) * 8;
    const u32 a_h_base = sbase + SM_WH + (u32)arow * 144 + (u32)aseg * 2;
    const u32 a_l_base = sbase + SM_WL + (u32)arow * 144 + (u32)aseg * 2;
    const u32 b_h_base = sbase + SM_XH + (u32)(lane & 15) * 272 + (u32)wc0 * 2;
    const u32 b_l_base = sbase + SM_XL + (u32)(lane & 15) * 272 + (u32)wc0 * 2;

#pragma unroll
    for (int ks = 0; ks < 4; ks++) {
        u32 bh[2][2], bl[2][2];
#pragma unroll
        for (int ni = 0; ni < 2; ni++) {
            ldm_x2t(bh[ni][0], bh[ni][1], b_h_base + (u32)(ks * 16) * 272 + (u32)ni * 16);
            ldm_x2t(bl[ni][0], bl[ni][1], b_l_base + (u32)(ks * 16) * 272 + (u32)ni * 16);
        }
#pragma unroll
        for (int mi = 0; mi < 4; mi++) {
            u32 ah[4], al[4];
            const u32 aoff = (u32)(mi * 16) * 144 + (u32)(ks * 16) * 2;
            ldm_x4(ah[0], ah[1], ah[2], ah[3], a_h_base + aoff);
            ldm_x4(al[0], al[1], al[2], al[3], a_l_base + aoff);
#pragma unroll
            for (int ni = 0; ni < 2; ni++) {
                mma_bf16(d[mi][ni], ah, bh[ni]);
                mma_bf16(d[mi][ni], ah, bl[ni]);
                mma_bf16(d[mi][ni], al, bh[ni]);
            }
        }
    }

    // ---- epilogue ----
    const float* dmean = (const float*)(smc + SM_DM);
    float* yb = y + (size_t)n * CHW + p0;
    const int nlo = (lane & 3) * 2;
    const int mrow = lane >> 2;
#pragma unroll
    for (int mi = 0; mi < 4; mi++) {
        const int ch0 = mi * 16 + mrow;
        const float dm0 = dmean[ch0];
        const float dm1 = dmean[ch0 + 8];
#pragma unroll
        for (int ni = 0; ni < 2; ni++) {
            const int col = wc0 + ni * 8 + nlo;
            float2 o0, o1;
            o0.x = d[mi][ni][0] - dm0; o0.y = d[mi][ni][1] - dm0;
            o1.x = d[mi][ni][2] - dm1; o1.y = d[mi][ni][3] - dm1;
            *(float2*)&yb[(size_t)ch0 * HW + col] = o0;
            *(float2*)&yb[(size_t)(ch0 + 8) * HW + col] = o1;
        }
    }
}

// =====================================================================
extern "C" void kernel_launch(void* const* d_in, const int* in_sizes, int n_in,
                              void* d_out, int out_size) {
    (void)in_sizes; (void)n_in; (void)out_size;
    const float* x = (const float*)d_in[0];
    float* y = (float*)d_out;

    cudaFuncSetAttribute(ns_kernel, cudaFuncAttributeMaxDynamicSharedMemorySize, NS_SMEM);
    cudaFuncSetAttribute(apply_mma_kernel, cudaFuncAttributeMaxDynamicSharedMemorySize, APPLY_SMEM);

    gram_kernel<<<GRID_GRAM, 256>>>(x);
    reduce_kernel<<<16, 256>>>();
    ns_kernel<<<1, 256, NS_SMEM>>>();
    apply_mma_kernel<<<GRID_APPLY, 256, APPLY_SMEM>>>(x, y);
}